// round 14
// baseline (speedup 1.0000x reference)
#include <cuda_runtime.h>
#include <cuda_bf16.h>
#include <cstdint>

#define MAXN 100000
#define MAXE 1600000
#define E2CAP (MAXE + MAXN + 16)
#define FPS 67108864.0f            // 2^26 fixed-point scale for weighted degree

// ---------------- device scratch (no allocations allowed) ----------------
// INVARIANT: g_pk is all-zero at kernel_launch entry (zero static init; k_scan3f
// re-zeroes each element after its single read, restoring the invariant per run).
__device__ unsigned long long g_pk[MAXN];   // packed: cnt<<46 | fixed-point weighted deg
__device__ float g_dinv[MAXN];
__device__ int   g_off[MAXN + 1];
__device__ int   g_cur[MAXN];
__device__ int   g_bsums[128];
__device__ __align__(16) unsigned long long g_erec[E2CAP];  // src(17)|dst(17)|norm(30)
__device__ float2 g_p[5][MAXN];     // states 1..4: p[k] = (A^k x, A^k 1)
__device__ float  g_c[6 * 128];     // coef rows: c5, d4, d3, d2, d1, b5

// ---------------- 8-byte edge record ----------------
__device__ __forceinline__ unsigned long long pack_rec(int s, int d, float nv) {
    return (unsigned long long)(unsigned)s
         | ((unsigned long long)(unsigned)d << 17)
         | ((unsigned long long)(__float_as_uint(nv) >> 2) << 34);
}
__device__ __forceinline__ void dec_rec(unsigned long long r, int& s, int& d, float& nv) {
    s = (int)(r & 0x1FFFFULL);
    d = (int)((r >> 17) & 0x1FFFFULL);
    nv = __uint_as_float((unsigned)(r >> 34) << 2);
}
__device__ __forceinline__ void dec_rec_sn(unsigned long long r, int& s, float& nv) {
    s = (int)(r & 0x1FFFFULL);
    nv = __uint_as_float((unsigned)(r >> 34) << 2);
}

// vector float2 atomic flush (sm_90+: single RED.64)
__device__ __forceinline__ void flush2(float2* addr, float ax, float ay) {
    atomicAdd(addr, make_float2(ax, ay));
}

// ---------------- preprocessing ----------------
// edge_index is int32 on device (JAX x64-disabled demotes int64).
// 4 edges/thread, vectorized input loads, 4 independent atomics in flight.
__global__ void k_edge_deg(int ecnt, const int* __restrict__ ei,
                           const float* __restrict__ ew) {
    int e = (blockIdx.x * blockDim.x + threadIdx.x) * 4;
    if (e + 4 <= ecnt) {
        int4   d4 = *(const int4*)&ei[ecnt + e];
        float4 w4 = *(const float4*)&ew[e];
        atomicAdd(&g_pk[d4.x], (unsigned long long)(w4.x * FPS + 0.5f) | (1ULL << 46));
        atomicAdd(&g_pk[d4.y], (unsigned long long)(w4.y * FPS + 0.5f) | (1ULL << 46));
        atomicAdd(&g_pk[d4.z], (unsigned long long)(w4.z * FPS + 0.5f) | (1ULL << 46));
        atomicAdd(&g_pk[d4.w], (unsigned long long)(w4.w * FPS + 0.5f) | (1ULL << 46));
    } else {
        for (int q = e; q < ecnt; q++) {
            atomicAdd(&g_pk[ei[ecnt + q]],
                      (unsigned long long)(ew[q] * FPS + 0.5f) | (1ULL << 46));
        }
    }
}

// warp-shuffle block scan (1024 threads, 2 barriers)
__global__ void k_scan1(int n) {
    __shared__ int wsum[32];
    int tid = threadIdx.x;
    int i = blockIdx.x * 1024 + tid;
    int v = (i < n) ? (int)(g_pk[i] >> 46) : 0;
    int lane = tid & 31, w = tid >> 5;
    int s = v;
    #pragma unroll
    for (int o = 1; o < 32; o <<= 1) {
        int t = __shfl_up_sync(0xffffffffu, s, o);
        if (lane >= o) s += t;
    }
    if (lane == 31) wsum[w] = s;
    __syncthreads();
    if (w == 0) {
        int ws = wsum[lane];
        #pragma unroll
        for (int o = 1; o < 32; o <<= 1) {
            int t = __shfl_up_sync(0xffffffffu, ws, o);
            if (lane >= o) ws += t;
        }
        wsum[lane] = ws;
    }
    __syncthreads();
    int incl = s + (w ? wsum[w - 1] : 0);
    if (i < n) g_off[i] = incl - v;
    if (tid == 1023) g_bsums[blockIdx.x] = incl;
}

// Fused: bsums scan + final offsets (+i self slots) + dinv + self-edge emit
//        + zero states + pads + RESTORE g_pk=0 for the next replay   (512 threads)
__global__ void k_scan3f(int n, int nb, int e2, int e2p) {
    __shared__ int sb[128];
    int tid = threadIdx.x;
    if (tid < 128) sb[tid] = (tid < nb) ? g_bsums[tid] : 0;
    __syncthreads();
    for (int off = 1; off < 128; off <<= 1) {
        int t = (tid >= off && tid < 128) ? sb[tid - off] : 0;
        __syncthreads();
        if (tid < 128) sb[tid] += t;
        __syncthreads();
    }
    if (blockIdx.x == 0) {
        if (tid == 0) g_off[n] = sb[nb - 1] + n;
        int p = e2 + tid;
        if (p < e2p) g_erec[p] = 0ULL;          // pads: src0,dst0,norm0 -> no-op
    }
    int i = blockIdx.x * blockDim.x + tid;
    if (i < n) {
        int blk = i >> 10;
        int o = g_off[i] + (blk ? sb[blk - 1] : 0) + i;   // +i: one self slot per prior node
        unsigned long long pk = g_pk[i];
        g_pk[i] = 0ULL;                          // restore invariant for next replay
        float deg = 1.0f + (float)(pk & ((1ULL << 46) - 1ULL)) * (1.0f / FPS);
        float di = rsqrtf(deg);
        float sn = di * di;
        g_dinv[i] = di;
        g_off[i] = o;
        g_cur[i] = o + 1;                       // real edges start after self edge
        g_erec[o] = pack_rec(i, i, sn);         // self edge at row head
        float2 z = make_float2(0.f, 0.f);       // p1 starts at zero: self term is IN the stream
        g_p[1][i] = z; g_p[2][i] = z; g_p[3][i] = z; g_p[4][i] = z;
    }
}

// 4 edges/thread: vectorized coalesced loads, 4 independent gather->atomic->store chains
__global__ void k_scatter(int ecnt, const int* __restrict__ ei,
                          const float* __restrict__ ew) {
    int e = (blockIdx.x * blockDim.x + threadIdx.x) * 4;
    if (e + 4 <= ecnt) {
        int4   s4 = *(const int4*)&ei[e];
        int4   d4 = *(const int4*)&ei[ecnt + e];
        float4 w4 = *(const float4*)&ew[e];
        float ds0 = __ldg(&g_dinv[s4.x]), ds1 = __ldg(&g_dinv[s4.y]);
        float ds2 = __ldg(&g_dinv[s4.z]), ds3 = __ldg(&g_dinv[s4.w]);
        float dd0 = __ldg(&g_dinv[d4.x]), dd1 = __ldg(&g_dinv[d4.y]);
        float dd2 = __ldg(&g_dinv[d4.z]), dd3 = __ldg(&g_dinv[d4.w]);
        int p0 = atomicAdd(&g_cur[d4.x], 1);
        int p1 = atomicAdd(&g_cur[d4.y], 1);
        int p2 = atomicAdd(&g_cur[d4.z], 1);
        int p3 = atomicAdd(&g_cur[d4.w], 1);
        g_erec[p0] = pack_rec(s4.x, d4.x, ds0 * w4.x * dd0);
        g_erec[p1] = pack_rec(s4.y, d4.y, ds1 * w4.y * dd1);
        g_erec[p2] = pack_rec(s4.z, d4.z, ds2 * w4.z * dd2);
        g_erec[p3] = pack_rec(s4.w, d4.w, ds3 * w4.w * dd3);
    } else {
        for (int q = e; q < ecnt; q++) {
            int s = ei[q], d = ei[ecnt + q];
            int pos = atomicAdd(&g_cur[d], 1);
            g_erec[pos] = pack_rec(s, d, g_dinv[s] * ew[q] * g_dinv[d]);
        }
    }
}

// ---------------- coefficient chain (device fn, run by block 0 of pass 1) ----------------
__device__ __forceinline__ void mv_row(const float* in, const float* W,
                                       int IN, int OUT, float* out, int j) {
    if (j < OUT) {
        float s = 0.0f;
        for (int k = 0; k < IN; k++) s += in[k] * W[k * OUT + j];
        out[j] = s;
    }
}

__device__ void weights_chain(const float* W1, const float* b1, const float* W2, const float* b2,
                              const float* W3, const float* b3, const float* W4, const float* b4,
                              const float* W5, const float* b5) {
    __shared__ float a[128], t[128];
    int j = threadIdx.x;

    if (j < 20) a[j] = W1[j];
    __syncthreads();
    mv_row(a, W2, 20, 40, t, j);  __syncthreads();
    mv_row(t, W3, 40, 60, a, j);  __syncthreads();
    mv_row(a, W4, 60, 80, t, j);  __syncthreads();
    mv_row(t, W5, 80, 100, &g_c[0 * 128], j); __syncthreads();

    if (j < 20) a[j] = b1[j];
    __syncthreads();
    mv_row(a, W2, 20, 40, t, j);  __syncthreads();
    mv_row(t, W3, 40, 60, a, j);  __syncthreads();
    mv_row(a, W4, 60, 80, t, j);  __syncthreads();
    mv_row(t, W5, 80, 100, &g_c[1 * 128], j); __syncthreads();

    if (j < 40) a[j] = b2[j];
    __syncthreads();
    mv_row(a, W3, 40, 60, t, j);  __syncthreads();
    mv_row(t, W4, 60, 80, a, j);  __syncthreads();
    mv_row(a, W5, 80, 100, &g_c[2 * 128], j); __syncthreads();

    if (j < 60) a[j] = b3[j];
    __syncthreads();
    mv_row(a, W4, 60, 80, t, j);  __syncthreads();
    mv_row(t, W5, 80, 100, &g_c[3 * 128], j); __syncthreads();

    if (j < 80) a[j] = b4[j];
    __syncthreads();
    mv_row(a, W5, 80, 100, &g_c[4 * 128], j); __syncthreads();

    if (j < 100) g_c[5 * 128 + j] = b5[j];
}

// 8-edge chunk for pass 1 (x gather), carrying run accumulator across chunks
__device__ __forceinline__ void chunk1(int t, const float* __restrict__ x,
                                       float2* out, int& cur, float& ax, float& ay) {
    ulonglong2 rA = *(const ulonglong2*)&g_erec[t];
    ulonglong2 rB = *(const ulonglong2*)&g_erec[t + 2];
    ulonglong2 rC = *(const ulonglong2*)&g_erec[t + 4];
    ulonglong2 rD = *(const ulonglong2*)&g_erec[t + 6];
    int ss[8], dd[8]; float cc[8];
    dec_rec(rA.x, ss[0], dd[0], cc[0]); dec_rec(rA.y, ss[1], dd[1], cc[1]);
    dec_rec(rB.x, ss[2], dd[2], cc[2]); dec_rec(rB.y, ss[3], dd[3], cc[3]);
    dec_rec(rC.x, ss[4], dd[4], cc[4]); dec_rec(rC.y, ss[5], dd[5], cc[5]);
    dec_rec(rD.x, ss[6], dd[6], cc[6]); dec_rec(rD.y, ss[7], dd[7], cc[7]);
    float vx[8];
    #pragma unroll
    for (int q = 0; q < 8; q++) vx[q] = cc[q] * __ldg(&x[ss[q]]);
    #pragma unroll
    for (int q = 0; q < 8; q++) {
        if (dd[q] == cur) { ax += vx[q]; ay += cc[q]; }
        else {
            if (cur >= 0) flush2(&out[cur], ax, ay);
            cur = dd[q]; ax = vx[q]; ay = cc[q];
        }
    }
}

// ---------------- pass 1 (edge-parallel, 16 edges/thread, run-merged) ----------------
__global__ void k_epass1(int e2, const float* __restrict__ x,
                         const float* __restrict__ W1, const float* __restrict__ b1,
                         const float* __restrict__ W2, const float* __restrict__ b2,
                         const float* __restrict__ W3, const float* __restrict__ b3,
                         const float* __restrict__ W4, const float* __restrict__ b4,
                         const float* __restrict__ W5, const float* __restrict__ b5) {
    if (blockIdx.x == 0)
        weights_chain(W1, b1, W2, b2, W3, b3, W4, b4, W5, b5);

    int t = (blockIdx.x * blockDim.x + threadIdx.x) * 16;
    if (t >= e2) return;
    float2* out = g_p[1];
    int cur = -1; float ax = 0.f, ay = 0.f;
    chunk1(t, x, out, cur, ax, ay);
    chunk1(t + 8, x, out, cur, ax, ay);
    flush2(&out[cur], ax, ay);
}

// 8-edge chunk for generic float2 pass
__device__ __forceinline__ void chunk2(int t, const float2* __restrict__ vin,
                                       float2* out, int& cur, float& ax, float& ay) {
    ulonglong2 rA = *(const ulonglong2*)&g_erec[t];
    ulonglong2 rB = *(const ulonglong2*)&g_erec[t + 2];
    ulonglong2 rC = *(const ulonglong2*)&g_erec[t + 4];
    ulonglong2 rD = *(const ulonglong2*)&g_erec[t + 6];
    int ss[8], dd[8]; float cc[8];
    dec_rec(rA.x, ss[0], dd[0], cc[0]); dec_rec(rA.y, ss[1], dd[1], cc[1]);
    dec_rec(rB.x, ss[2], dd[2], cc[2]); dec_rec(rB.y, ss[3], dd[3], cc[3]);
    dec_rec(rC.x, ss[4], dd[4], cc[4]); dec_rec(rC.y, ss[5], dd[5], cc[5]);
    dec_rec(rD.x, ss[6], dd[6], cc[6]); dec_rec(rD.y, ss[7], dd[7], cc[7]);
    float vx[8], vy[8];
    #pragma unroll
    for (int q = 0; q < 8; q++) {
        float2 w = __ldg(&vin[ss[q]]);
        vx[q] = cc[q] * w.x;
        vy[q] = cc[q] * w.y;
    }
    #pragma unroll
    for (int q = 0; q < 8; q++) {
        if (dd[q] == cur) { ax += vx[q]; ay += vy[q]; }
        else {
            if (cur >= 0) flush2(&out[cur], ax, ay);
            cur = dd[q]; ax = vx[q]; ay = vy[q];
        }
    }
}

// ---------------- generic pass (edge-parallel, 16 edges/thread, run-merged) ----------------
__global__ void k_epass(int e2, int kin, int kout) {
    int t = (blockIdx.x * blockDim.x + threadIdx.x) * 16;
    if (t >= e2) return;
    const float2* __restrict__ vin = g_p[kin];
    float2* out = g_p[kout];
    int cur = -1; float ax = 0.f, ay = 0.f;
    chunk2(t, vin, out, cur, ax, ay);
    chunk2(t + 8, vin, out, cur, ax, ay);
    flush2(&out[cur], ax, ay);
}

// ---------------- pass 5 (x-only, node-parallel pull; row includes self edge) + final write ----------------
__global__ void k_spmv5_final(int n, float* __restrict__ out) {
    __shared__ float sc[6][100];
    __shared__ float sv5[256], sa1[256], sa2[256], sa3[256], sa4[256];
    for (int t = threadIdx.x; t < 600; t += blockDim.x)
        sc[t / 100][t % 100] = g_c[(t / 100) * 128 + (t % 100)];

    int base = blockIdx.x * 256;
    int i = base + threadIdx.x;

    if (i < n) {
        const float2* __restrict__ vin = g_p[4];
        int e0 = g_off[i], e1 = g_off[i + 1];
        float ax = 0.0f;                         // self edge is in the row
        int e = e0;
        for (; e + 4 <= e1; e += 4) {
            unsigned long long r0 = __ldg(&g_erec[e]);
            unsigned long long r1 = __ldg(&g_erec[e + 1]);
            unsigned long long r2 = __ldg(&g_erec[e + 2]);
            unsigned long long r3 = __ldg(&g_erec[e + 3]);
            int s0, s1, s2, s3; float c0, c1, c2, c3;
            dec_rec_sn(r0, s0, c0); dec_rec_sn(r1, s1, c1);
            dec_rec_sn(r2, s2, c2); dec_rec_sn(r3, s3, c3);
            float v0 = __ldg(&vin[s0].x);
            float v1 = __ldg(&vin[s1].x);
            float v2 = __ldg(&vin[s2].x);
            float v3 = __ldg(&vin[s3].x);
            ax += c0 * v0 + c1 * v1 + c2 * v2 + c3 * v3;
        }
        for (; e < e1; e++) {
            int s; float c;
            dec_rec_sn(__ldg(&g_erec[e]), s, c);
            ax += c * __ldg(&vin[s].x);
        }
        sv5[threadIdx.x] = ax;
        sa1[threadIdx.x] = g_p[1][i].y;
        sa2[threadIdx.x] = g_p[2][i].y;
        sa3[threadIdx.x] = g_p[3][i].y;
        sa4[threadIdx.x] = g_p[4][i].y;
    }
    __syncthreads();

    for (int t = threadIdx.x; t < 256 * 25; t += blockDim.x) {
        int wnode = t / 25;
        int ch = t - wnode * 25;
        int node = base + wnode;
        if (node >= n) break;
        float v5 = sv5[wnode];
        float a1 = sa1[wnode], a2 = sa2[wnode], a3 = sa3[wnode], a4 = sa4[wnode];
        int j0 = ch * 4;
        float4 r;
        float* rr = &r.x;
        #pragma unroll
        for (int q = 0; q < 4; q++) {
            int j = j0 + q;
            rr[q] = fmaxf(v5 * sc[0][j] + a4 * sc[1][j] + a3 * sc[2][j]
                        + a2 * sc[3][j] + a1 * sc[4][j] + sc[5][j], 0.0f);
        }
        ((float4*)(out + (size_t)node * 100))[ch] = r;
    }
}

// ---------------- launch ----------------
extern "C" void kernel_launch(void* const* d_in, const int* in_sizes, int n_in,
                              void* d_out, int out_size) {
    const float* x  = (const float*)d_in[0];
    const int*   ei = (const int*)d_in[1];     // int32! (JAX demotes int64)
    const float* ew = (const float*)d_in[2];
    const float* W1 = (const float*)d_in[3];  const float* b1 = (const float*)d_in[4];
    const float* W2 = (const float*)d_in[5];  const float* b2 = (const float*)d_in[6];
    const float* W3 = (const float*)d_in[7];  const float* b3 = (const float*)d_in[8];
    const float* W4 = (const float*)d_in[9];  const float* b4 = (const float*)d_in[10];
    const float* W5 = (const float*)d_in[11]; const float* b5 = (const float*)d_in[12];
    float* out = (float*)d_out;

    int n = in_sizes[0];
    int e = in_sizes[2];
    int e2 = e + n;                    // edges + self loops
    int e2p = (e2 + 15) & ~15;         // padded to 16

    int tb = 256;
    int gbN  = (n + tb - 1) / tb;
    int gbN5 = (n + 511) / 512;
    int nb   = (n + 1023) / 1024;
    int gbE4 = ((e + 3) / 4 + tb - 1) / tb;     // 4 edges/thread kernels
    int tE   = (e2 + 15) / 16;                  // one thread per 16 edges
    int gbE2 = (tE + tb - 1) / tb;

    k_edge_deg<<<gbE4, tb>>>(e, ei, ew);
    k_scan1<<<nb, 1024>>>(n);
    k_scan3f<<<gbN5, 512>>>(n, nb, e2, e2p);
    k_scatter<<<gbE4, tb>>>(e, ei, ew);

    k_epass1<<<gbE2, tb>>>(e2, x, W1, b1, W2, b2, W3, b3, W4, b4, W5, b5);
    k_epass<<<gbE2, tb>>>(e2, 1, 2);
    k_epass<<<gbE2, tb>>>(e2, 2, 3);
    k_epass<<<gbE2, tb>>>(e2, 3, 4);
    k_spmv5_final<<<gbN, tb>>>(n, out);

    (void)n_in; (void)out_size;
}

// round 15
// speedup vs baseline: 1.0299x; 1.0299x over previous
#include <cuda_runtime.h>
#include <cuda_bf16.h>
#include <cstdint>

#define MAXN 100000
#define MAXE 1600000
#define E2CAP (MAXE + MAXN + 16)
#define FPS 67108864.0f            // 2^26 fixed-point scale for weighted degree

// ---------------- device scratch (no allocations allowed) ----------------
// INVARIANT: g_pk is all-zero at kernel_launch entry (zero static init; k_scan3f
// re-zeroes each element after its single read, restoring the invariant per run).
__device__ unsigned long long g_pk[MAXN];   // packed: cnt<<46 | fixed-point weighted deg
__device__ float g_dinv[MAXN];
__device__ int   g_off[MAXN + 1];
__device__ int   g_cur[MAXN];
__device__ int   g_bsums[128];
__device__ __align__(16) unsigned long long g_erec[E2CAP];  // src(17)|dst(17)|RAW weight(30)
// States v_k = D^{1/2} p_k as float4 {vx, vy, dinv2, pad}. dinv2 rides in .z so the
// per-edge gather gets value+scale in ONE 16B load (same 1 sector as float2).
// Atomic flush touches only the first 8B, so .z persists across accumulation.
__device__ __align__(16) float4 g_s[5][MAXN];   // states 0..4 (pass 5 fused in final)
__device__ float  g_c[6 * 128];                  // coef rows: c5, d4, d3, d2, d1, b5

// ---------------- 8-byte edge record (raw weight; NO node data needed) ----------------
__device__ __forceinline__ unsigned long long pack_rec(int s, int d, float w) {
    return (unsigned long long)(unsigned)s
         | ((unsigned long long)(unsigned)d << 17)
         | ((unsigned long long)(__float_as_uint(w) >> 2) << 34);
}
__device__ __forceinline__ void dec_rec(unsigned long long r, int& s, int& d, float& w) {
    s = (int)(r & 0x1FFFFULL);
    d = (int)((r >> 17) & 0x1FFFFULL);
    w = __uint_as_float((unsigned)(r >> 34) << 2);
}
__device__ __forceinline__ void dec_rec_sn(unsigned long long r, int& s, float& w) {
    s = (int)(r & 0x1FFFFULL);
    w = __uint_as_float((unsigned)(r >> 34) << 2);
}

// vector float2 atomic flush (sm_90+: single RED.64)
__device__ __forceinline__ void flush2(float4* addr, float ax, float ay) {
    atomicAdd((float2*)addr, make_float2(ax, ay));
}

// ---------------- preprocessing ----------------
// edge_index is int32 on device (JAX x64-disabled demotes int64).
__global__ void k_edge_deg(int ecnt, const int* __restrict__ ei,
                           const float* __restrict__ ew) {
    int e = blockIdx.x * blockDim.x + threadIdx.x;
    if (e < ecnt) {
        int d = ei[ecnt + e];
        unsigned long long v = (unsigned long long)(ew[e] * FPS + 0.5f) | (1ULL << 46);
        atomicAdd(&g_pk[d], v);
    }
}

// warp-shuffle block scan (1024 threads, 2 barriers)
__global__ void k_scan1(int n) {
    __shared__ int wsum[32];
    int tid = threadIdx.x;
    int i = blockIdx.x * 1024 + tid;
    int v = (i < n) ? (int)(g_pk[i] >> 46) : 0;
    int lane = tid & 31, w = tid >> 5;
    int s = v;
    #pragma unroll
    for (int o = 1; o < 32; o <<= 1) {
        int t = __shfl_up_sync(0xffffffffu, s, o);
        if (lane >= o) s += t;
    }
    if (lane == 31) wsum[w] = s;
    __syncthreads();
    if (w == 0) {
        int ws = wsum[lane];
        #pragma unroll
        for (int o = 1; o < 32; o <<= 1) {
            int t = __shfl_up_sync(0xffffffffu, ws, o);
            if (lane >= o) ws += t;
        }
        wsum[lane] = ws;
    }
    __syncthreads();
    int incl = s + (w ? wsum[w - 1] : 0);
    if (i < n) g_off[i] = incl - v;
    if (tid == 1023) g_bsums[blockIdx.x] = incl;
}

// Fused: bsums scan + final offsets (+i self slots) + dinv + self-edge (w=1) +
//        state0 = {x*sqrt(deg), sqrt(deg), dinv2} + zero states 1..4 (keeping .z=dinv2)
//        + pads + RESTORE g_pk=0 for the next replay
__global__ void k_scan3f(int n, int nb, int e2, int e2p, const float* __restrict__ x) {
    __shared__ int sb[128];
    int tid = threadIdx.x;
    if (tid < 128) sb[tid] = (tid < nb) ? g_bsums[tid] : 0;
    __syncthreads();
    for (int off = 1; off < 128; off <<= 1) {
        int t = (tid >= off && tid < 128) ? sb[tid - off] : 0;
        __syncthreads();
        if (tid < 128) sb[tid] += t;
        __syncthreads();
    }
    if (blockIdx.x == 0) {
        if (tid == 0) g_off[n] = sb[nb - 1] + n;
        int p = e2 + tid;
        if (p < e2p) g_erec[p] = 0ULL;          // pads: w=0 -> no-op contribution
    }
    int i = blockIdx.x * blockDim.x + tid;
    if (i < n) {
        int blk = i >> 10;
        int o = g_off[i] + (blk ? sb[blk - 1] : 0) + i;   // +i: one self slot per prior node
        unsigned long long pk = g_pk[i];
        g_pk[i] = 0ULL;                          // restore invariant for next replay
        float deg = 1.0f + (float)(pk & ((1ULL << 46) - 1ULL)) * (1.0f / FPS);
        float di = rsqrtf(deg);
        float d2 = di * di;
        float sq = deg * di;                     // sqrt(deg)
        g_dinv[i] = di;
        g_off[i] = o;
        g_cur[i] = o + 1;                        // real edges start after self edge
        g_erec[o] = pack_rec(i, i, 1.0f);        // self edge, RAW weight 1 (exact in 30b)
        g_s[0][i] = make_float4(sq * __ldg(&x[i]), sq, d2, 0.0f);   // v0 = D^{1/2}(x,1)
        float4 z = make_float4(0.f, 0.f, d2, 0.f);
        g_s[1][i] = z; g_s[2][i] = z; g_s[3][i] = z; g_s[4][i] = z;
    }
}

// ---------------- coefficient chain (device fn; runs in scatter's block 0) ----------------
__device__ __forceinline__ void mv_row(const float* in, const float* W,
                                       int IN, int OUT, float* out, int j) {
    if (j < OUT) {
        float s = 0.0f;
        for (int k = 0; k < IN; k++) s += in[k] * W[k * OUT + j];
        out[j] = s;
    }
}

__device__ void weights_chain(const float* W1, const float* b1, const float* W2, const float* b2,
                              const float* W3, const float* b3, const float* W4, const float* b4,
                              const float* W5, const float* b5) {
    __shared__ float a[128], t[128];
    int j = threadIdx.x;

    if (j < 20) a[j] = W1[j];
    __syncthreads();
    mv_row(a, W2, 20, 40, t, j);  __syncthreads();
    mv_row(t, W3, 40, 60, a, j);  __syncthreads();
    mv_row(a, W4, 60, 80, t, j);  __syncthreads();
    mv_row(t, W5, 80, 100, &g_c[0 * 128], j); __syncthreads();

    if (j < 20) a[j] = b1[j];
    __syncthreads();
    mv_row(a, W2, 20, 40, t, j);  __syncthreads();
    mv_row(t, W3, 40, 60, a, j);  __syncthreads();
    mv_row(a, W4, 60, 80, t, j);  __syncthreads();
    mv_row(t, W5, 80, 100, &g_c[1 * 128], j); __syncthreads();

    if (j < 40) a[j] = b2[j];
    __syncthreads();
    mv_row(a, W3, 40, 60, t, j);  __syncthreads();
    mv_row(t, W4, 60, 80, a, j);  __syncthreads();
    mv_row(a, W5, 80, 100, &g_c[2 * 128], j); __syncthreads();

    if (j < 60) a[j] = b3[j];
    __syncthreads();
    mv_row(a, W4, 60, 80, t, j);  __syncthreads();
    mv_row(t, W5, 80, 100, &g_c[3 * 128], j); __syncthreads();

    if (j < 80) a[j] = b4[j];
    __syncthreads();
    mv_row(a, W5, 80, 100, &g_c[4 * 128], j); __syncthreads();

    if (j < 100) g_c[5 * 128 + j] = b5[j];
}

// ---------------- scatter: NO node gathers — just position atomic + 8B record ----------------
__global__ void k_scatter(int ecnt, const int* __restrict__ ei, const float* __restrict__ ew,
                          const float* __restrict__ W1, const float* __restrict__ b1,
                          const float* __restrict__ W2, const float* __restrict__ b2,
                          const float* __restrict__ W3, const float* __restrict__ b3,
                          const float* __restrict__ W4, const float* __restrict__ b4,
                          const float* __restrict__ W5, const float* __restrict__ b5) {
    if (blockIdx.x == 0)
        weights_chain(W1, b1, W2, b2, W3, b3, W4, b4, W5, b5);  // hidden under scatter

    int e = blockIdx.x * blockDim.x + threadIdx.x;
    if (e < ecnt) {
        int s = ei[e];
        int d = ei[ecnt + e];
        int pos = atomicAdd(&g_cur[d], 1);
        g_erec[pos] = pack_rec(s, d, ew[e]);
    }
}

// 8-edge chunk: gather float4 state (value + dinv2 in one sector), run-merged flush
__device__ __forceinline__ void chunk(int t, const float4* __restrict__ vin,
                                      float4* out, int& cur, float& ax, float& ay) {
    ulonglong2 rA = *(const ulonglong2*)&g_erec[t];
    ulonglong2 rB = *(const ulonglong2*)&g_erec[t + 2];
    ulonglong2 rC = *(const ulonglong2*)&g_erec[t + 4];
    ulonglong2 rD = *(const ulonglong2*)&g_erec[t + 6];
    int ss[8], dd[8]; float cc[8];
    dec_rec(rA.x, ss[0], dd[0], cc[0]); dec_rec(rA.y, ss[1], dd[1], cc[1]);
    dec_rec(rB.x, ss[2], dd[2], cc[2]); dec_rec(rB.y, ss[3], dd[3], cc[3]);
    dec_rec(rC.x, ss[4], dd[4], cc[4]); dec_rec(rC.y, ss[5], dd[5], cc[5]);
    dec_rec(rD.x, ss[6], dd[6], cc[6]); dec_rec(rD.y, ss[7], dd[7], cc[7]);
    float vx[8], vy[8];
    #pragma unroll
    for (int q = 0; q < 8; q++) {
        float4 w = __ldg(&vin[ss[q]]);
        float cd = cc[q] * w.z;         // raw weight * dinv2[src]
        vx[q] = cd * w.x;
        vy[q] = cd * w.y;
    }
    #pragma unroll
    for (int q = 0; q < 8; q++) {
        if (dd[q] == cur) { ax += vx[q]; ay += vy[q]; }
        else {
            if (cur >= 0) flush2(&out[cur], ax, ay);
            cur = dd[q]; ax = vx[q]; ay = vy[q];
        }
    }
}

// ---------------- generic pass (edge-parallel, 16 edges/thread, run-merged) ----------------
__global__ void k_epass(int e2, int kin, int kout) {
    int t = (blockIdx.x * blockDim.x + threadIdx.x) * 16;
    if (t >= e2) return;
    const float4* __restrict__ vin = g_s[kin];
    float4* out = g_s[kout];
    int cur = -1; float ax = 0.f, ay = 0.f;
    chunk(t, vin, out, cur, ax, ay);
    chunk(t + 8, vin, out, cur, ax, ay);
    flush2(&out[cur], ax, ay);
}

// ---------------- pass 5 (x-only, node-parallel pull) + final write ----------------
__global__ void k_spmv5_final(int n, float* __restrict__ out) {
    __shared__ float sc[6][100];
    __shared__ float sv5[256], sa1[256], sa2[256], sa3[256], sa4[256];
    for (int t = threadIdx.x; t < 600; t += blockDim.x)
        sc[t / 100][t % 100] = g_c[(t / 100) * 128 + (t % 100)];

    int base = blockIdx.x * 256;
    int i = base + threadIdx.x;

    if (i < n) {
        const float4* __restrict__ vin = g_s[4];
        int e0 = g_off[i], e1 = g_off[i + 1];
        float ax = 0.0f;                         // self edge is in the row
        int e = e0;
        for (; e + 4 <= e1; e += 4) {
            unsigned long long r0 = __ldg(&g_erec[e]);
            unsigned long long r1 = __ldg(&g_erec[e + 1]);
            unsigned long long r2 = __ldg(&g_erec[e + 2]);
            unsigned long long r3 = __ldg(&g_erec[e + 3]);
            int s0, s1, s2, s3; float c0, c1, c2, c3;
            dec_rec_sn(r0, s0, c0); dec_rec_sn(r1, s1, c1);
            dec_rec_sn(r2, s2, c2); dec_rec_sn(r3, s3, c3);
            float4 v0 = __ldg(&vin[s0]);
            float4 v1 = __ldg(&vin[s1]);
            float4 v2 = __ldg(&vin[s2]);
            float4 v3 = __ldg(&vin[s3]);
            ax += c0 * v0.z * v0.x + c1 * v1.z * v1.x
                + c2 * v2.z * v2.x + c3 * v3.z * v3.x;
        }
        for (; e < e1; e++) {
            int s; float c;
            dec_rec_sn(__ldg(&g_erec[e]), s, c);
            float4 v = __ldg(&vin[s]);
            ax += c * v.z * v.x;
        }
        float di = g_dinv[i];                    // un-scale: p_k = D^{-1/2} v_k
        sv5[threadIdx.x] = di * ax;
        sa1[threadIdx.x] = di * g_s[1][i].y;
        sa2[threadIdx.x] = di * g_s[2][i].y;
        sa3[threadIdx.x] = di * g_s[3][i].y;
        sa4[threadIdx.x] = di * g_s[4][i].y;
    }
    __syncthreads();

    for (int t = threadIdx.x; t < 256 * 25; t += blockDim.x) {
        int wnode = t / 25;
        int ch = t - wnode * 25;
        int node = base + wnode;
        if (node >= n) break;
        float v5 = sv5[wnode];
        float a1 = sa1[wnode], a2 = sa2[wnode], a3 = sa3[wnode], a4 = sa4[wnode];
        int j0 = ch * 4;
        float4 r;
        float* rr = &r.x;
        #pragma unroll
        for (int q = 0; q < 4; q++) {
            int j = j0 + q;
            rr[q] = fmaxf(v5 * sc[0][j] + a4 * sc[1][j] + a3 * sc[2][j]
                        + a2 * sc[3][j] + a1 * sc[4][j] + sc[5][j], 0.0f);
        }
        ((float4*)(out + (size_t)node * 100))[ch] = r;
    }
}

// ---------------- launch ----------------
extern "C" void kernel_launch(void* const* d_in, const int* in_sizes, int n_in,
                              void* d_out, int out_size) {
    const float* x  = (const float*)d_in[0];
    const int*   ei = (const int*)d_in[1];     // int32! (JAX demotes int64)
    const float* ew = (const float*)d_in[2];
    const float* W1 = (const float*)d_in[3];  const float* b1 = (const float*)d_in[4];
    const float* W2 = (const float*)d_in[5];  const float* b2 = (const float*)d_in[6];
    const float* W3 = (const float*)d_in[7];  const float* b3 = (const float*)d_in[8];
    const float* W4 = (const float*)d_in[9];  const float* b4 = (const float*)d_in[10];
    const float* W5 = (const float*)d_in[11]; const float* b5 = (const float*)d_in[12];
    float* out = (float*)d_out;

    int n = in_sizes[0];
    int e = in_sizes[2];
    int e2 = e + n;                    // edges + self loops
    int e2p = (e2 + 15) & ~15;         // padded to 16

    int tb = 256;
    int gbN  = (n + tb - 1) / tb;
    int gbE  = (e + tb - 1) / tb;
    int nb   = (n + 1023) / 1024;
    int tE   = (e2 + 15) / 16;         // one thread per 16 edges
    int gbE2 = (tE + tb - 1) / tb;

    k_edge_deg<<<gbE, tb>>>(e, ei, ew);
    k_scan1<<<nb, 1024>>>(n);
    k_scan3f<<<gbN, tb>>>(n, nb, e2, e2p, x);
    k_scatter<<<gbE, tb>>>(e, ei, ew, W1, b1, W2, b2, W3, b3, W4, b4, W5, b5);

    k_epass<<<gbE2, tb>>>(e2, 0, 1);
    k_epass<<<gbE2, tb>>>(e2, 1, 2);
    k_epass<<<gbE2, tb>>>(e2, 2, 3);
    k_epass<<<gbE2, tb>>>(e2, 3, 4);
    k_spmv5_final<<<gbN, tb>>>(n, out);

    (void)n_in; (void)out_size;
}